// round 4
// baseline (speedup 1.0000x reference)
#include <cuda_runtime.h>
#include <math.h>

#define B_  8
#define T_  4096
#define H_  4
#define HV_ 8
#define K_  128
#define V_  128
#define REP_ (HV_/H_)   // 2

// Scratch (static __device__ arrays: allocation-free per harness rules)
__device__ float g_qn[(size_t)B_*T_*H_*K_];   // l2-normalized q * K^-0.5
__device__ float g_kn[(size_t)B_*T_*H_*K_];   // l2-normalized k
__device__ float g_g [(size_t)B_*T_*HV_];     // log-decay
__device__ float g_bt[(size_t)B_*T_*HV_];     // sigmoid(b)

// ---------------------------------------------------------------------------
// Prepass 1: per (b,t,h) row — l2norm q and k over K=128, fold in scale on q.
// 4 warps per block, one row per warp.
// ---------------------------------------------------------------------------
__global__ void __launch_bounds__(128) prep_qk(const float* __restrict__ q,
                                               const float* __restrict__ k) {
    int warp = threadIdx.x >> 5;
    int lane = threadIdx.x & 31;
    size_t row = (size_t)blockIdx.x * 4 + warp;   // (b*T+t)*H + h, grid sized exactly
    const float4* q4 = reinterpret_cast<const float4*>(q + row * K_);
    const float4* k4 = reinterpret_cast<const float4*>(k + row * K_);
    float4 qa = q4[lane];
    float4 ka = k4[lane];
    float sq = qa.x*qa.x + qa.y*qa.y + qa.z*qa.z + qa.w*qa.w;
    float sk = ka.x*ka.x + ka.y*ka.y + ka.z*ka.z + ka.w*ka.w;
    #pragma unroll
    for (int o = 16; o > 0; o >>= 1) {
        sq += __shfl_xor_sync(0xffffffffu, sq, o);
        sk += __shfl_xor_sync(0xffffffffu, sk, o);
    }
    const float scale = 0.088388347648318440550f;   // 128^-0.5
    float iq = rsqrtf(sq + 1e-6f) * scale;
    float ik = rsqrtf(sk + 1e-6f);
    float4 qo = make_float4(qa.x*iq, qa.y*iq, qa.z*iq, qa.w*iq);
    float4 ko = make_float4(ka.x*ik, ka.y*ik, ka.z*ik, ka.w*ik);
    reinterpret_cast<float4*>(g_qn + row * K_)[lane] = qo;
    reinterpret_cast<float4*>(g_kn + row * K_)[lane] = ko;
}

// ---------------------------------------------------------------------------
// Prepass 2: per (b,t,hv) — gate g = -exp(A_log)*softplus(a+dt_bias), beta.
// ---------------------------------------------------------------------------
__global__ void __launch_bounds__(256) prep_gate(const float* __restrict__ A_log,
                                                 const float* __restrict__ a,
                                                 const float* __restrict__ dt_bias,
                                                 const float* __restrict__ b) {
    size_t i = (size_t)blockIdx.x * blockDim.x + threadIdx.x;
    if (i >= (size_t)B_*T_*HV_) return;
    int hv = (int)(i % HV_);
    float x = a[i] + dt_bias[hv];
    float sp = (x <= 20.0f) ? log1pf(expf(x)) : x;   // softplus, beta=1, thr=20
    g_g[i]  = -expf(A_log[hv]) * sp;
    g_bt[i] = 1.0f / (1.0f + expf(-b[i]));
}

// ---------------------------------------------------------------------------
// Main persistent recurrence.
// grid = B*HV*2 = 128 CTAs, 128 threads.
//   blockIdx.x: bit0 = v-half, bits[1:3] = hv, bits[4:6] = b
//   thread: kh = tid&1 (K-half), col = tid>>1 (local V column)
// Each thread holds 64 state registers h[k in K-half][v]. K-reduction via
// shfl_xor(1) with the partner lane. No __syncthreads in the T loop.
// ---------------------------------------------------------------------------
__global__ void __launch_bounds__(128, 1) gdn_recurrent(
    const float* __restrict__ vin,
    const float* __restrict__ h0src,
    const int*   __restrict__ h0idx,
    float* __restrict__ out)
{
    int blk   = blockIdx.x;
    int vhalf = blk & 1;
    int hv    = (blk >> 1) & (HV_ - 1);
    int b     = blk >> 4;
    int tid   = threadIdx.x;
    int kh    = tid & 1;
    int col   = tid >> 1;
    int v     = vhalf * 64 + col;
    int hh    = hv / REP_;

    float h[64];
    int idx = h0idx[b];
    if (idx >= 0) {
        const float* src = h0src + (((size_t)idx * HV_ + hv) * K_ + (size_t)kh * 64) * V_ + v;
        #pragma unroll
        for (int i = 0; i < 64; i++) h[i] = src[(size_t)i * V_];
    } else {
        #pragma unroll
        for (int i = 0; i < 64; i++) h[i] = 0.0f;
    }

    const float* knb = g_kn + ((size_t)b * T_ * H_ + hh) * K_ + (size_t)kh * 64;
    const float* qnb = g_qn + ((size_t)b * T_ * H_ + hh) * K_ + (size_t)kh * 64;
    const float* vp  = vin  + ((size_t)b * T_ * HV_ + hv) * V_ + v;
    const float* gp  = g_g  + (size_t)b * T_ * HV_ + hv;
    const float* bp  = g_bt + (size_t)b * T_ * HV_ + hv;
    float*       op  = out  + ((size_t)b * T_ * HV_ + hv) * V_ + v;

    for (int t = 0; t < T_; t++) {
        float eg   = expf(gp[0]);
        float beta = bp[0];
        float vt   = vp[0];

        const float4* k4 = reinterpret_cast<const float4*>(knb);
        float4 kc[16];
        #pragma unroll
        for (int j = 0; j < 16; j++) kc[j] = k4[j];

        // Pass A: decay state, accumulate kv = sum_k h_dec[k]*k[k] (this K-half)
        float kv0 = 0.f, kv1 = 0.f, kv2 = 0.f, kv3 = 0.f;
        #pragma unroll
        for (int j = 0; j < 16; j++) {
            h[4*j+0] *= eg; kv0 = fmaf(h[4*j+0], kc[j].x, kv0);
            h[4*j+1] *= eg; kv1 = fmaf(h[4*j+1], kc[j].y, kv1);
            h[4*j+2] *= eg; kv2 = fmaf(h[4*j+2], kc[j].z, kv2);
            h[4*j+3] *= eg; kv3 = fmaf(h[4*j+3], kc[j].w, kv3);
        }
        float kv = (kv0 + kv1) + (kv2 + kv3);
        kv += __shfl_xor_sync(0xffffffffu, kv, 1);   // combine the two K-halves
        float u = (vt - kv) * beta;

        // Pass B: rank-1 update + output dot with q
        const float4* q4 = reinterpret_cast<const float4*>(qnb);
        float o0 = 0.f, o1 = 0.f, o2 = 0.f, o3 = 0.f;
        #pragma unroll
        for (int j = 0; j < 16; j++) {
            float4 qc = q4[j];
            h[4*j+0] = fmaf(kc[j].x, u, h[4*j+0]); o0 = fmaf(h[4*j+0], qc.x, o0);
            h[4*j+1] = fmaf(kc[j].y, u, h[4*j+1]); o1 = fmaf(h[4*j+1], qc.y, o1);
            h[4*j+2] = fmaf(kc[j].z, u, h[4*j+2]); o2 = fmaf(h[4*j+2], qc.z, o2);
            h[4*j+3] = fmaf(kc[j].w, u, h[4*j+3]); o3 = fmaf(h[4*j+3], qc.w, o3);
        }
        float o = (o0 + o1) + (o2 + o3);
        o += __shfl_xor_sync(0xffffffffu, o, 1);
        if (kh == 0) *op = o;

        knb += H_ * K_;
        qnb += H_ * K_;
        vp  += HV_ * V_;
        gp  += HV_;
        bp  += HV_;
        op  += HV_ * V_;
    }
}

// ---------------------------------------------------------------------------
// Inputs (metadata order): A_log, a, dt_bias, q, k, v, b,
//                          initial_state_source, initial_state_indices
// Output: float32 [B,T,HV,V]
// ---------------------------------------------------------------------------
extern "C" void kernel_launch(void* const* d_in, const int* in_sizes, int n_in,
                              void* d_out, int out_size) {
    const float* A_log = (const float*)d_in[0];
    const float* a     = (const float*)d_in[1];
    const float* dtb   = (const float*)d_in[2];
    const float* q     = (const float*)d_in[3];
    const float* k     = (const float*)d_in[4];
    const float* v     = (const float*)d_in[5];
    const float* bb    = (const float*)d_in[6];
    const float* h0    = (const float*)d_in[7];
    const int*   h0i   = (const int*)d_in[8];
    float* out = (float*)d_out;

    // Prepass 1: B*T*H rows, 4 rows per 128-thread block
    prep_qk<<<(B_ * T_ * H_) / 4, 128>>>(q, k);
    // Prepass 2: B*T*HV gate elements
    prep_gate<<<((size_t)B_ * T_ * HV_ + 255) / 256, 256>>>(A_log, a, dtb, bb);
    // Main persistent recurrence
    gdn_recurrent<<<B_ * HV_ * 2, 128>>>(v, h0, h0i, out);
}